// round 11
// baseline (speedup 1.0000x reference)
#include <cuda_runtime.h>
#include <cuda_bf16.h>
#include <cstdint>

#define Bsz 32
#define Tn  2048
#define Ff  512
#define EPSL 1e-5f
#define NELT (Bsz*Tn*Ff)

// ---------------- scratch ----------------
__device__ float g_A[NELT];                     // fp32 master activations (residual stream)
__device__ float g_Q[NELT];
__device__ float g_K[NELT];
__device__ float g_V[NELT];
__device__ __nv_bfloat16 g_Dh[NELT], g_Dl[NELT];   // bf16 hi/lo GEMM A-operand
__device__ __nv_bfloat16 g_Wh[7*512*512], g_Wl[7*512*512];
__device__ float g_pe[Bsz*Ff];
__device__ float g_bsum[Bsz], g_bsqs[Bsz];
__device__ float g_tsum[Tn],  g_tsqs[Tn];

// ---------------- helpers ----------------
__device__ __forceinline__ uint32_t smem_u32(const void* p) {
    uint32_t a;
    asm("{ .reg .u64 t; cvta.to.shared.u64 t, %1; cvt.u32.u64 %0, t; }" : "=r"(a) : "l"(p));
    return a;
}
__device__ __forceinline__ void cp16(uint32_t dst, const void* src) {
    asm volatile("cp.async.cg.shared.global [%0], [%1], 16;" :: "r"(dst), "l"(src) : "memory");
}
#define CP_COMMIT() asm volatile("cp.async.commit_group;" ::: "memory")
template<int N> __device__ __forceinline__ void cp_wait() {
    asm volatile("cp.async.wait_group %0;" :: "n"(N) : "memory");
}
__device__ __forceinline__ void ldmx4(uint32_t* r, uint32_t a) {
    asm volatile("ldmatrix.sync.aligned.m8n8.x4.shared.b16 {%0,%1,%2,%3}, [%4];"
        : "=r"(r[0]), "=r"(r[1]), "=r"(r[2]), "=r"(r[3]) : "r"(a));
}
__device__ __forceinline__ void mmabf(float* c, const uint32_t* a, uint32_t b0, uint32_t b1) {
    asm volatile("mma.sync.aligned.m16n8k16.row.col.f32.bf16.bf16.f32 "
        "{%0,%1,%2,%3}, {%4,%5,%6,%7}, {%8,%9}, {%0,%1,%2,%3};"
        : "+f"(c[0]), "+f"(c[1]), "+f"(c[2]), "+f"(c[3])
        : "r"(a[0]), "r"(a[1]), "r"(a[2]), "r"(a[3]), "r"(b0), "r"(b1));
}
#define SWZ(o) ((o) ^ (((o) >> 3) & 0x70))
__device__ __forceinline__ uint32_t packbf(float lo, float hi) {
    uint32_t r;
    asm("cvt.rn.bf16x2.f32 %0, %1, %2;" : "=r"(r) : "f"(hi), "f"(lo));
    return r;
}
// split float4 -> hi/lo bf16 pairs (h01,h23,l01,l23)
__device__ __forceinline__ void split4(float4 v, uint2& h, uint2& l) {
    uint32_t h01 = packbf(v.x, v.y), h23 = packbf(v.z, v.w);
    float hx = __uint_as_float(h01 << 16), hy = __uint_as_float(h01 & 0xFFFF0000u);
    float hz = __uint_as_float(h23 << 16), hw = __uint_as_float(h23 & 0xFFFF0000u);
    h = make_uint2(h01, h23);
    l = make_uint2(packbf(v.x - hx, v.y - hy), packbf(v.z - hz, v.w - hw));
}

// ---------------- glue kernels ----------------
__global__ void k_zero2(float* a, float* b, int n) {
    int i = blockIdx.x * blockDim.x + threadIdx.x;
    if (i < n) { a[i] = 0.f; b[i] = 0.f; }
}

__global__ void k_pe(float* pe) {
    int i = blockIdx.x * 256 + threadIdx.x;
    int e = i & 511, b = i >> 9;
    float div = expf(-9.210340371976184f * (float)(e & ~1) / 512.0f);
    float arg = (float)b * div;
    pe[i] = (e & 1) ? cosf(arg) : sinf(arg);
}

__global__ void k_addpe(const float* __restrict__ in, const float* __restrict__ pe, float* __restrict__ out) {
    size_t i4 = (size_t)blockIdx.x * 1024 + threadIdx.x;
    size_t i = i4 * 4;
    int e = (int)(i & 511), b = (int)(i >> 20);
    float4 x = ((const float4*)in)[i4];
    float4 p = *(const float4*)(pe + (b << 9) + e);
    x.x += p.x; x.y += p.y; x.z += p.z; x.w += p.w;
    ((float4*)out)[i4] = x;
}

__global__ void k_wconv(const float* __restrict__ src, __nv_bfloat16* __restrict__ h, __nv_bfloat16* __restrict__ l) {
    int i = blockIdx.x * 256 + threadIdx.x;   // 65536 float4
    float4 v = ((const float4*)src)[i];
    uint2 hh, ll; split4(v, hh, ll);
    ((uint2*)h)[i] = hh; ((uint2*)l)[i] = ll;
}

__global__ void k_bstats(const float* __restrict__ x, float* __restrict__ sum, float* __restrict__ sqs) {
    int b = blockIdx.x;
    const float* p = x + (size_t)b * Ff * Tn;
    int per = (Ff * Tn) / gridDim.y;
    int base = blockIdx.y * per;
    float s = 0.f, q = 0.f;
    for (int i = threadIdx.x; i < per; i += blockDim.x) {
        float v = p[base + i]; s += v; q += v * v;
    }
    __shared__ float ss[8], qq[8];
    for (int o = 16; o > 0; o >>= 1) { s += __shfl_down_sync(~0u, s, o); q += __shfl_down_sync(~0u, q, o); }
    if ((threadIdx.x & 31) == 0) { ss[threadIdx.x >> 5] = s; qq[threadIdx.x >> 5] = q; }
    __syncthreads();
    if (threadIdx.x < 8) {
        s = ss[threadIdx.x]; q = qq[threadIdx.x];
        for (int o = 4; o > 0; o >>= 1) { s += __shfl_down_sync(0xffu, s, o); q += __shfl_down_sync(0xffu, q, o); }
        if (threadIdx.x == 0) { atomicAdd(&sum[b], s); atomicAdd(&sqs[b], q); }
    }
}

__global__ void k_tstats(const float* __restrict__ x, float* __restrict__ sum, float* __restrict__ sqs) {
    int t = blockIdx.x;
    float s = 0.f, q = 0.f;
    for (int b = 0; b < Bsz; b++) {
        const float* p = x + ((size_t)b * Tn + t) * Ff;
        for (int i = threadIdx.x; i < Ff; i += 256) { float v = p[i]; s += v; q += v * v; }
    }
    __shared__ float ss[8], qq[8];
    for (int o = 16; o > 0; o >>= 1) { s += __shfl_down_sync(~0u, s, o); q += __shfl_down_sync(~0u, q, o); }
    if ((threadIdx.x & 31) == 0) { ss[threadIdx.x >> 5] = s; qq[threadIdx.x >> 5] = q; }
    __syncthreads();
    if (threadIdx.x < 8) {
        s = ss[threadIdx.x]; q = qq[threadIdx.x];
        for (int o = 4; o > 0; o >>= 1) { s += __shfl_down_sync(0xffu, s, o); q += __shfl_down_sync(0xffu, q, o); }
        if (threadIdx.x == 0) { sum[t] = s; sqs[t] = q; }
    }
}

// per-batch LN -> bf16 hi/lo split
__global__ void k_lnb(const float* __restrict__ x, const float* __restrict__ sum, const float* __restrict__ sqs,
                      __nv_bfloat16* __restrict__ oh, __nv_bfloat16* __restrict__ ol) {
    size_t i4 = (size_t)blockIdx.x * 256 + threadIdx.x;
    int b = (int)(i4 >> 18);
    const float inv = 1.0f / (float)(Ff * Tn);
    float mu = sum[b] * inv;
    float rs = rsqrtf(sqs[b] * inv - mu * mu + EPSL);
    float4 v = ((const float4*)x)[i4];
    v.x = (v.x - mu) * rs; v.y = (v.y - mu) * rs; v.z = (v.z - mu) * rs; v.w = (v.w - mu) * rs;
    uint2 h, l; split4(v, h, l);
    ((uint2*)oh)[i4] = h; ((uint2*)ol)[i4] = l;
}

// per-token LN -> bf16 hi/lo split
__global__ void k_lnt(const float* __restrict__ x, const float* __restrict__ sum, const float* __restrict__ sqs,
                      __nv_bfloat16* __restrict__ oh, __nv_bfloat16* __restrict__ ol) {
    size_t i4 = (size_t)blockIdx.x * 256 + threadIdx.x;
    int t = (int)((i4 >> 7) & 2047);
    const float inv = 1.0f / (float)(Bsz * Ff);
    float mu = sum[t] * inv;
    float rs = rsqrtf(sqs[t] * inv - mu * mu + EPSL);
    float4 v = ((const float4*)x)[i4];
    v.x = (v.x - mu) * rs; v.y = (v.y - mu) * rs; v.z = (v.z - mu) * rs; v.w = (v.w - mu) * rs;
    uint2 h, l; split4(v, h, l);
    ((uint2*)oh)[i4] = h; ((uint2*)ol)[i4] = l;
}

// fused per-batch LN + depthwise conv (K=7, pad 3) -> bf16 hi/lo
__global__ void k_dw(const float* __restrict__ x, const float* __restrict__ sum,
                     const float* __restrict__ sqs, const float* __restrict__ w,
                     const float* __restrict__ bias,
                     __nv_bfloat16* __restrict__ oh, __nv_bfloat16* __restrict__ ol) {
    int bb = blockIdx.y, t0 = blockIdx.x * 16;
    int tid = threadIdx.x;   // 128 threads, each owns 4 feature cols f = tid*4
    __shared__ float4 s[22][128];
    const float inv = 1.0f / (float)(Ff * Tn);
    float mu = sum[bb] * inv;
    float rs = rsqrtf(sqs[bb] * inv - mu * mu + EPSL);
    const float4* p = (const float4*)(x + (size_t)bb * Tn * Ff);
#pragma unroll
    for (int tt = 0; tt < 22; tt++) {
        int t = t0 + tt - 3;
        float4 v = make_float4(0.f, 0.f, 0.f, 0.f);
        if (t >= 0 && t < Tn) {
            v = p[(size_t)t * 128 + tid];
            v.x = (v.x - mu) * rs; v.y = (v.y - mu) * rs;
            v.z = (v.z - mu) * rs; v.w = (v.w - mu) * rs;
        }
        s[tt][tid] = v;
    }
    __syncthreads();
    float wr[4][7];
#pragma unroll
    for (int q = 0; q < 4; q++)
#pragma unroll
        for (int k = 0; k < 7; k++) wr[q][k] = w[(tid * 4 + q) * 7 + k];
    float4 bv = *(const float4*)(bias + tid * 4);
#pragma unroll
    for (int j = 0; j < 16; j++) {
        float4 acc = bv;
#pragma unroll
        for (int k = 0; k < 7; k++) {
            float4 vv = s[j + k][tid];
            acc.x += wr[0][k] * vv.x; acc.y += wr[1][k] * vv.y;
            acc.z += wr[2][k] * vv.z; acc.w += wr[3][k] * vv.w;
        }
        uint2 h, l; split4(acc, h, l);
        size_t row = (size_t)bb * Tn + t0 + j;
        ((uint2*)(oh + row * Ff))[tid] = h;
        ((uint2*)(ol + row * Ff))[tid] = l;
    }
}

// batch-axis attention: per (t,h) 32x32 softmax(QK^T/8) @ V -> bf16 hi/lo
__global__ void k_attn(const float* __restrict__ Q, const float* __restrict__ K,
                       const float* __restrict__ V,
                       __nv_bfloat16* __restrict__ oh, __nv_bfloat16* __restrict__ ol) {
    int t = blockIdx.x, h = blockIdx.y;
    __shared__ float qs[32][65], ks[32][65], vs[32][65], ps[32][33];
    int tid = threadIdx.y * 32 + threadIdx.x;
    for (int i = tid; i < 2048; i += 1024) {
        int b = i >> 6, d = i & 63;
        size_t a = ((size_t)b * Tn + t) * Ff + h * 64 + d;
        qs[b][d] = Q[a]; ks[b][d] = K[a]; vs[b][d] = V[a];
    }
    __syncthreads();
    int c = threadIdx.x, r = threadIdx.y;
    float s = 0.f;
#pragma unroll 16
    for (int d = 0; d < 64; d++) s += qs[r][d] * ks[c][d];
    s *= 0.125f;
    float m = s;
    for (int o = 16; o > 0; o >>= 1) m = fmaxf(m, __shfl_xor_sync(~0u, m, o));
    float e = expf(s - m);
    float sm = e;
    for (int o = 16; o > 0; o >>= 1) sm += __shfl_xor_sync(~0u, sm, o);
    ps[r][c] = e / sm;
    __syncthreads();
    float a0 = 0.f, a1 = 0.f;
#pragma unroll 8
    for (int cc = 0; cc < 32; cc++) {
        float p = ps[r][cc];
        a0 += p * vs[cc][c];
        a1 += p * vs[cc][c + 32];
    }
    size_t ob = ((size_t)r * Tn + t) * Ff + h * 64;
    __nv_bfloat16 h0 = __float2bfloat16(a0);
    __nv_bfloat16 h1 = __float2bfloat16(a1);
    oh[ob + c]      = h0;  ol[ob + c]      = __float2bfloat16(a0 - __bfloat162float(h0));
    oh[ob + c + 32] = h1;  ol[ob + c + 32] = __float2bfloat16(a1 - __bfloat162float(h1));
}

// ---------------- bf16x3 HMMA GEMM ----------------
// out[r, n] = sum_f A[r,f]*W[n,f] + bias[n] (+ res[r,n])
// A,W pre-split bf16 hi/lo. Block 128x128, warps 2(m)x4(n), warp tile 64x32, K-chunk 64, 2-stage cp.async.
#define SMS 65536
__global__ void __launch_bounds__(256, 1)
k_gemm(const __nv_bfloat16* __restrict__ Ah, const __nv_bfloat16* __restrict__ Al,
       const __nv_bfloat16* __restrict__ Wh, const __nv_bfloat16* __restrict__ Wl,
       const float* __restrict__ bias, const float* __restrict__ res, float* __restrict__ out)
{
    extern __shared__ __align__(1024) char smem[];
    const uint32_t sb = smem_u32(smem);
    const int tid = threadIdx.x, lane = tid & 31, wid = tid >> 5;
    const int n0 = blockIdx.x * 128;
    const size_t r0 = (size_t)blockIdx.y * 128;

    auto issue = [&](int i, int s) {
        int k0 = i * 64;
        uint32_t st = sb + s * SMS;
#pragma unroll
        for (int j = 0; j < 4; j++) {
            int u = tid + j * 256;
            int row = u >> 3, kg = u & 7;
            uint32_t off = SWZ((uint32_t)(row * 128 + kg * 16));
            size_t ga = (r0 + row) * 512 + k0 + kg * 8;
            size_t gb = (size_t)(n0 + row) * 512 + k0 + kg * 8;
            cp16(st + off,         Ah + ga);
            cp16(st + 16384 + off, Al + ga);
            cp16(st + 32768 + off, Wh + gb);
            cp16(st + 49152 + off, Wl + gb);
        }
        CP_COMMIT();
    };

    float acc[4][4][4];
#pragma unroll
    for (int a = 0; a < 4; a++)
#pragma unroll
        for (int b = 0; b < 4; b++)
#pragma unroll
            for (int d = 0; d < 4; d++) acc[a][b][d] = 0.f;

    issue(0, 0); issue(1, 1);

    const int wm = (wid & 1) * 64, wn = (wid >> 1) * 32;
    const int grp = lane >> 3, l7 = lane & 7;
    const int a_row = (grp & 1) * 8 + l7, a_kb = (grp >> 1) * 16;
    const int b_n   = (grp >> 1) * 8 + l7, b_kb = (grp & 1) * 16;

    for (int i = 0; i < 8; i++) {
        const int s = i & 1;
        if (i == 7) cp_wait<0>(); else cp_wait<1>();
        __syncthreads();
        const uint32_t stA = sb + s * SMS, stAl = stA + 16384, stBh = stA + 32768, stBl = stA + 49152;
#pragma unroll
        for (int ki = 0; ki < 4; ki++) {
            uint32_t ah[4][4], al[4][4], bh[4][2], bl[4][2];
#pragma unroll
            for (int mi = 0; mi < 4; mi++) {
                uint32_t off = SWZ((uint32_t)((wm + mi * 16 + a_row) * 128 + ki * 32 + a_kb));
                ldmx4(ah[mi], stA + off);
                ldmx4(al[mi], stAl + off);
            }
#pragma unroll
            for (int pi = 0; pi < 2; pi++) {
                uint32_t off = SWZ((uint32_t)((wn + pi * 16 + b_n) * 128 + ki * 32 + b_kb));
                uint32_t r[4];
                ldmx4(r, stBh + off);
                bh[pi*2][0] = r[0]; bh[pi*2][1] = r[1]; bh[pi*2+1][0] = r[2]; bh[pi*2+1][1] = r[3];
                ldmx4(r, stBl + off);
                bl[pi*2][0] = r[0]; bl[pi*2][1] = r[1]; bl[pi*2+1][0] = r[2]; bl[pi*2+1][1] = r[3];
            }
#pragma unroll
            for (int mi = 0; mi < 4; mi++)
#pragma unroll
                for (int ni = 0; ni < 4; ni++) {
                    mmabf(acc[mi][ni], ah[mi], bh[ni][0], bh[ni][1]);
                    mmabf(acc[mi][ni], ah[mi], bl[ni][0], bl[ni][1]);
                    mmabf(acc[mi][ni], al[mi], bh[ni][0], bh[ni][1]);
                }
        }
        __syncthreads();
        if (i + 2 < 8) issue(i + 2, s);
    }

    // epilogue: direct fp32 stores with bias (+res)
    const int erow = lane >> 2, ecol = (lane & 3) * 2;
#pragma unroll
    for (int mi = 0; mi < 4; mi++) {
        size_t row0 = r0 + wm + mi * 16 + erow;
#pragma unroll
        for (int ni = 0; ni < 4; ni++) {
            int col = n0 + wn + ni * 8 + ecol;
            float2 bv = *(const float2*)(bias + col);
            float2 o0 = make_float2(acc[mi][ni][0] + bv.x, acc[mi][ni][1] + bv.y);
            float2 o1 = make_float2(acc[mi][ni][2] + bv.x, acc[mi][ni][3] + bv.y);
            size_t i0 = row0 * 512 + col, i1 = (row0 + 8) * 512 + col;
            if (res) {
                float2 r0v = *(const float2*)(res + i0), r1v = *(const float2*)(res + i1);
                o0.x += r0v.x; o0.y += r0v.y; o1.x += r1v.x; o1.y += r1v.y;
            }
            *(float2*)(out + i0) = o0;
            *(float2*)(out + i1) = o1;
        }
    }
}

// ---------------- host ----------------
extern "C" void kernel_launch(void* const* d_in, const int* in_sizes, int n_in,
                              void* d_out, int out_size) {
    const float* x     = (const float*)d_in[0];
    const float* dw1_w = (const float*)d_in[1];
    const float* dw1_b = (const float*)d_in[2];
    const float* pw1_w = (const float*)d_in[3];
    const float* pw1_b = (const float*)d_in[4];
    const float* dw2_w = (const float*)d_in[5];
    const float* dw2_b = (const float*)d_in[6];
    const float* pw2_w = (const float*)d_in[7];
    const float* pw2_b = (const float*)d_in[8];
    const float* wq = (const float*)d_in[9];
    const float* bq = (const float*)d_in[10];
    const float* wk = (const float*)d_in[11];
    const float* bk = (const float*)d_in[12];
    const float* wv = (const float*)d_in[13];
    const float* bv = (const float*)d_in[14];
    const float* wp = (const float*)d_in[15];
    const float* bp = (const float*)d_in[16];
    const float* ff_w = (const float*)d_in[17];
    const float* ff_b = (const float*)d_in[18];
    float* out = (float*)d_out;

    float *A, *Q, *K, *V, *pe, *bsum, *bsqs, *tsum, *tsqs;
    __nv_bfloat16 *Dh, *Dl, *Wh, *Wl;
    cudaGetSymbolAddress((void**)&A,  g_A);
    cudaGetSymbolAddress((void**)&Q,  g_Q);
    cudaGetSymbolAddress((void**)&K,  g_K);
    cudaGetSymbolAddress((void**)&V,  g_V);
    cudaGetSymbolAddress((void**)&Dh, g_Dh);
    cudaGetSymbolAddress((void**)&Dl, g_Dl);
    cudaGetSymbolAddress((void**)&Wh, g_Wh);
    cudaGetSymbolAddress((void**)&Wl, g_Wl);
    cudaGetSymbolAddress((void**)&pe, g_pe);
    cudaGetSymbolAddress((void**)&bsum, g_bsum);
    cudaGetSymbolAddress((void**)&bsqs, g_bsqs);
    cudaGetSymbolAddress((void**)&tsum, g_tsum);
    cudaGetSymbolAddress((void**)&tsqs, g_tsqs);

    cudaFuncSetAttribute(k_gemm, cudaFuncAttributeMaxDynamicSharedMemorySize, 2 * SMS);

    const int WSZ = 512 * 512;
    dim3 gemmGrid(4, 512);
    dim3 dwGrid(Tn / 16, Bsz);
    dim3 bsGrid(Bsz, 64);

    // weights -> bf16 hi/lo (order: pw1, pw2, wq, wk, wv, wp, ff)
    k_wconv<<<256, 256>>>(pw1_w, Wh + 0*WSZ, Wl + 0*WSZ);
    k_wconv<<<256, 256>>>(pw2_w, Wh + 1*WSZ, Wl + 1*WSZ);
    k_wconv<<<256, 256>>>(wq,    Wh + 2*WSZ, Wl + 2*WSZ);
    k_wconv<<<256, 256>>>(wk,    Wh + 3*WSZ, Wl + 3*WSZ);
    k_wconv<<<256, 256>>>(wv,    Wh + 4*WSZ, Wl + 4*WSZ);
    k_wconv<<<256, 256>>>(wp,    Wh + 5*WSZ, Wl + 5*WSZ);
    k_wconv<<<256, 256>>>(ff_w,  Wh + 6*WSZ, Wl + 6*WSZ);

    // 1) x + pe
    k_pe<<<64, 256>>>(pe);
    k_addpe<<<NELT/4096, 1024>>>(x, pe, A);

    // 2) LN + conv1 + pointwise1
    k_zero2<<<1, 32>>>(bsum, bsqs, Bsz);
    k_bstats<<<bsGrid, 256>>>(A, bsum, bsqs);
    k_dw<<<dwGrid, 128>>>(A, bsum, bsqs, dw1_w, dw1_b, Dh, Dl);
    k_gemm<<<gemmGrid, 256, 2*SMS>>>(Dh, Dl, Wh + 0*WSZ, Wl + 0*WSZ, pw1_b, nullptr, A);

    // 3) 3x residual conv blocks (shared weights)
    for (int it = 0; it < 3; it++) {
        k_zero2<<<1, 32>>>(bsum, bsqs, Bsz);
        k_bstats<<<bsGrid, 256>>>(A, bsum, bsqs);
        k_dw<<<dwGrid, 128>>>(A, bsum, bsqs, dw2_w, dw2_b, Dh, Dl);
        k_gemm<<<gemmGrid, 256, 2*SMS>>>(Dh, Dl, Wh + 1*WSZ, Wl + 1*WSZ, pw2_b, A, A);
    }

    // 4) per-batch LN -> split, then QKV projections
    k_zero2<<<1, 32>>>(bsum, bsqs, Bsz);
    k_bstats<<<bsGrid, 256>>>(A, bsum, bsqs);
    k_lnb<<<NELT/1024, 256>>>(A, bsum, bsqs, Dh, Dl);
    k_gemm<<<gemmGrid, 256, 2*SMS>>>(Dh, Dl, Wh + 2*WSZ, Wl + 2*WSZ, bq, nullptr, Q);
    k_gemm<<<gemmGrid, 256, 2*SMS>>>(Dh, Dl, Wh + 3*WSZ, Wl + 3*WSZ, bk, nullptr, K);
    k_gemm<<<gemmGrid, 256, 2*SMS>>>(Dh, Dl, Wh + 4*WSZ, Wl + 4*WSZ, bv, nullptr, V);

    // 5) batch-axis attention -> split operand
    k_attn<<<dim3(Tn, 8), dim3(32, 32)>>>(Q, K, V, Dh, Dl);

    // 6) output projection + residual
    k_gemm<<<gemmGrid, 256, 2*SMS>>>(Dh, Dl, Wh + 5*WSZ, Wl + 5*WSZ, bp, A, A);

    // 7) final per-token LN -> split, FF + residual -> d_out
    k_tstats<<<Tn, 256>>>(A, tsum, tsqs);
    k_lnt<<<NELT/1024, 256>>>(A, tsum, tsqs, Dh, Dl);
    k_gemm<<<gemmGrid, 256, 2*SMS>>>(Dh, Dl, Wh + 6*WSZ, Wl + 6*WSZ, ff_b, A, out);
}

// round 13
// speedup vs baseline: 1.5201x; 1.5201x over previous
#include <cuda_runtime.h>
#include <cuda_bf16.h>
#include <cstdint>

#define Bsz 32
#define Tn  2048
#define Ff  512
#define EPSL 1e-5f
#define NELT (Bsz*Tn*Ff)

// ---------------- scratch ----------------
__device__ float g_A[NELT];
__device__ float g_Q[NELT];
__device__ float g_K[NELT];
__device__ float g_V[NELT];
__device__ __nv_bfloat16 g_Dh[NELT], g_Dl[NELT];
__device__ __nv_bfloat16 g_Wh[7*512*512], g_Wl[7*512*512];
__device__ float g_pe[Bsz*Ff];
__device__ float g_bsum[Bsz], g_bsqs[Bsz];
__device__ float g_tsum[Tn],  g_tsqs[Tn];

// ---------------- helpers ----------------
__device__ __forceinline__ uint32_t smem_u32(const void* p) {
    uint32_t a;
    asm("{ .reg .u64 t; cvta.to.shared.u64 t, %1; cvt.u32.u64 %0, t; }" : "=r"(a) : "l"(p));
    return a;
}
__device__ __forceinline__ void cp16(uint32_t dst, const void* src) {
    asm volatile("cp.async.cg.shared.global [%0], [%1], 16;" :: "r"(dst), "l"(src) : "memory");
}
#define CP_COMMIT() asm volatile("cp.async.commit_group;" ::: "memory")
template<int N> __device__ __forceinline__ void cp_wait() {
    asm volatile("cp.async.wait_group %0;" :: "n"(N) : "memory");
}
__device__ __forceinline__ void ldmx4(uint32_t* r, uint32_t a) {
    asm volatile("ldmatrix.sync.aligned.m8n8.x4.shared.b16 {%0,%1,%2,%3}, [%4];"
        : "=r"(r[0]), "=r"(r[1]), "=r"(r[2]), "=r"(r[3]) : "r"(a));
}
__device__ __forceinline__ void mmabf(float* c, const uint32_t* a, uint32_t b0, uint32_t b1) {
    asm volatile("mma.sync.aligned.m16n8k16.row.col.f32.bf16.bf16.f32 "
        "{%0,%1,%2,%3}, {%4,%5,%6,%7}, {%8,%9}, {%0,%1,%2,%3};"
        : "+f"(c[0]), "+f"(c[1]), "+f"(c[2]), "+f"(c[3])
        : "r"(a[0]), "r"(a[1]), "r"(a[2]), "r"(a[3]), "r"(b0), "r"(b1));
}
#define SWZ64(o) ((o) ^ (((o) >> 3) & 0x30))
__device__ __forceinline__ uint32_t packbf(float lo, float hi) {
    uint32_t r;
    asm("cvt.rn.bf16x2.f32 %0, %1, %2;" : "=r"(r) : "f"(hi), "f"(lo));
    return r;
}
__device__ __forceinline__ void split4(float4 v, uint2& h, uint2& l) {
    uint32_t h01 = packbf(v.x, v.y), h23 = packbf(v.z, v.w);
    float hx = __uint_as_float(h01 << 16), hy = __uint_as_float(h01 & 0xFFFF0000u);
    float hz = __uint_as_float(h23 << 16), hw = __uint_as_float(h23 & 0xFFFF0000u);
    h = make_uint2(h01, h23);
    l = make_uint2(packbf(v.x - hx, v.y - hy), packbf(v.z - hz, v.w - hw));
}

// ---------------- glue kernels ----------------
__global__ void k_zero2(float* a, float* b, int n) {
    int i = blockIdx.x * blockDim.x + threadIdx.x;
    if (i < n) { a[i] = 0.f; b[i] = 0.f; }
}

__global__ void k_pe(float* pe) {
    int i = blockIdx.x * 256 + threadIdx.x;
    int e = i & 511, b = i >> 9;
    float div = expf(-9.210340371976184f * (float)(e & ~1) / 512.0f);
    float arg = (float)b * div;
    pe[i] = (e & 1) ? cosf(arg) : sinf(arg);
}

// x + pe, fused per-batch stats (each block's 4096 elems lie in one batch)
__global__ void k_addpe(const float* __restrict__ in, const float* __restrict__ pe,
                        float* __restrict__ out, float* __restrict__ bsum, float* __restrict__ bsqs) {
    size_t i4 = (size_t)blockIdx.x * 1024 + threadIdx.x;
    size_t i = i4 * 4;
    int e = (int)(i & 511), b = (int)(i >> 20);
    float4 x = ((const float4*)in)[i4];
    float4 p = *(const float4*)(pe + (b << 9) + e);
    x.x += p.x; x.y += p.y; x.z += p.z; x.w += p.w;
    ((float4*)out)[i4] = x;
    float s = x.x + x.y + x.z + x.w;
    float q = x.x*x.x + x.y*x.y + x.z*x.z + x.w*x.w;
    for (int o = 16; o > 0; o >>= 1) { s += __shfl_down_sync(~0u, s, o); q += __shfl_down_sync(~0u, q, o); }
    __shared__ float rs_[32], rq_[32];
    int w = threadIdx.x >> 5;
    if ((threadIdx.x & 31) == 0) { rs_[w] = s; rq_[w] = q; }
    __syncthreads();
    if (threadIdx.x == 0) {
        s = 0.f; q = 0.f;
        for (int j = 0; j < 32; j++) { s += rs_[j]; q += rq_[j]; }
        atomicAdd(&bsum[b], s); atomicAdd(&bsqs[b], q);
    }
}

// 7 weight matrices -> bf16 hi/lo in one launch
__global__ void k_wconv7(const float* s0, const float* s1, const float* s2, const float* s3,
                         const float* s4, const float* s5, const float* s6,
                         __nv_bfloat16* __restrict__ h, __nv_bfloat16* __restrict__ l) {
    const float* srcs[7] = { s0, s1, s2, s3, s4, s5, s6 };
    int w = blockIdx.y;
    size_t base = (size_t)w * 65536;
    int i = blockIdx.x * 256 + threadIdx.x;
    float4 v = ((const float4*)srcs[w])[i];
    uint2 hh, ll; split4(v, hh, ll);
    ((uint2*)h)[base + i] = hh; ((uint2*)l)[base + i] = ll;
}

__global__ void k_tstats(const float* __restrict__ x, float* __restrict__ sum, float* __restrict__ sqs) {
    int t = blockIdx.x;
    float s = 0.f, q = 0.f;
    for (int b = 0; b < Bsz; b++) {
        const float* p = x + ((size_t)b * Tn + t) * Ff;
        for (int i = threadIdx.x; i < Ff; i += 256) { float v = p[i]; s += v; q += v * v; }
    }
    __shared__ float ss[8], qq[8];
    for (int o = 16; o > 0; o >>= 1) { s += __shfl_down_sync(~0u, s, o); q += __shfl_down_sync(~0u, q, o); }
    if ((threadIdx.x & 31) == 0) { ss[threadIdx.x >> 5] = s; qq[threadIdx.x >> 5] = q; }
    __syncthreads();
    if (threadIdx.x < 8) {
        s = ss[threadIdx.x]; q = qq[threadIdx.x];
        for (int o = 4; o > 0; o >>= 1) { s += __shfl_down_sync(0xffu, s, o); q += __shfl_down_sync(0xffu, q, o); }
        if (threadIdx.x == 0) { sum[t] = s; sqs[t] = q; }
    }
}

__global__ void k_lnb(const float* __restrict__ x, const float* __restrict__ sum, const float* __restrict__ sqs,
                      __nv_bfloat16* __restrict__ oh, __nv_bfloat16* __restrict__ ol) {
    size_t i4 = (size_t)blockIdx.x * 256 + threadIdx.x;
    int b = (int)(i4 >> 18);
    const float inv = 1.0f / (float)(Ff * Tn);
    float mu = sum[b] * inv;
    float rs = rsqrtf(sqs[b] * inv - mu * mu + EPSL);
    float4 v = ((const float4*)x)[i4];
    v.x = (v.x - mu) * rs; v.y = (v.y - mu) * rs; v.z = (v.z - mu) * rs; v.w = (v.w - mu) * rs;
    uint2 h, l; split4(v, h, l);
    ((uint2*)oh)[i4] = h; ((uint2*)ol)[i4] = l;
}

__global__ void k_lnt(const float* __restrict__ x, const float* __restrict__ sum, const float* __restrict__ sqs,
                      __nv_bfloat16* __restrict__ oh, __nv_bfloat16* __restrict__ ol) {
    size_t i4 = (size_t)blockIdx.x * 256 + threadIdx.x;
    int t = (int)((i4 >> 7) & 2047);
    const float inv = 1.0f / (float)(Bsz * Ff);
    float mu = sum[t] * inv;
    float rs = rsqrtf(sqs[t] * inv - mu * mu + EPSL);
    float4 v = ((const float4*)x)[i4];
    v.x = (v.x - mu) * rs; v.y = (v.y - mu) * rs; v.z = (v.z - mu) * rs; v.w = (v.w - mu) * rs;
    uint2 h, l; split4(v, h, l);
    ((uint2*)oh)[i4] = h; ((uint2*)ol)[i4] = l;
}

// per-batch LN + depthwise conv (K=7, pad 3) -> bf16 hi/lo
__global__ void k_dw(const float* __restrict__ x, const float* __restrict__ sum,
                     const float* __restrict__ sqs, const float* __restrict__ w,
                     const float* __restrict__ bias,
                     __nv_bfloat16* __restrict__ oh, __nv_bfloat16* __restrict__ ol) {
    int bb = blockIdx.y, t0 = blockIdx.x * 16;
    int tid = threadIdx.x;
    __shared__ float4 s[22][128];
    const float inv = 1.0f / (float)(Ff * Tn);
    float mu = sum[bb] * inv;
    float rs = rsqrtf(sqs[bb] * inv - mu * mu + EPSL);
    const float4* p = (const float4*)(x + (size_t)bb * Tn * Ff);
#pragma unroll
    for (int tt = 0; tt < 22; tt++) {
        int t = t0 + tt - 3;
        float4 v = make_float4(0.f, 0.f, 0.f, 0.f);
        if (t >= 0 && t < Tn) {
            v = p[(size_t)t * 128 + tid];
            v.x = (v.x - mu) * rs; v.y = (v.y - mu) * rs;
            v.z = (v.z - mu) * rs; v.w = (v.w - mu) * rs;
        }
        s[tt][tid] = v;
    }
    __syncthreads();
    float wr[4][7];
#pragma unroll
    for (int q = 0; q < 4; q++)
#pragma unroll
        for (int k = 0; k < 7; k++) wr[q][k] = w[(tid * 4 + q) * 7 + k];
    float4 bv = *(const float4*)(bias + tid * 4);
#pragma unroll
    for (int j = 0; j < 16; j++) {
        float4 acc = bv;
#pragma unroll
        for (int k = 0; k < 7; k++) {
            float4 vv = s[j + k][tid];
            acc.x += wr[0][k] * vv.x; acc.y += wr[1][k] * vv.y;
            acc.z += wr[2][k] * vv.z; acc.w += wr[3][k] * vv.w;
        }
        uint2 h, l; split4(acc, h, l);
        size_t row = (size_t)bb * Tn + t0 + j;
        ((uint2*)(oh + row * Ff))[tid] = h;
        ((uint2*)(ol + row * Ff))[tid] = l;
    }
}

// batch-axis attention -> bf16 hi/lo
__global__ void k_attn(const float* __restrict__ Q, const float* __restrict__ K,
                       const float* __restrict__ V,
                       __nv_bfloat16* __restrict__ oh, __nv_bfloat16* __restrict__ ol) {
    int t = blockIdx.x, h = blockIdx.y;
    __shared__ float qs[32][65], ks[32][65], vs[32][65], ps[32][33];
    int tid = threadIdx.y * 32 + threadIdx.x;
    for (int i = tid; i < 2048; i += 1024) {
        int b = i >> 6, d = i & 63;
        size_t a = ((size_t)b * Tn + t) * Ff + h * 64 + d;
        qs[b][d] = Q[a]; ks[b][d] = K[a]; vs[b][d] = V[a];
    }
    __syncthreads();
    int c = threadIdx.x, r = threadIdx.y;
    float s = 0.f;
#pragma unroll 16
    for (int d = 0; d < 64; d++) s += qs[r][d] * ks[c][d];
    s *= 0.125f;
    float m = s;
    for (int o = 16; o > 0; o >>= 1) m = fmaxf(m, __shfl_xor_sync(~0u, m, o));
    float e = expf(s - m);
    float sm = e;
    for (int o = 16; o > 0; o >>= 1) sm += __shfl_xor_sync(~0u, sm, o);
    ps[r][c] = e / sm;
    __syncthreads();
    float a0 = 0.f, a1 = 0.f;
#pragma unroll 8
    for (int cc = 0; cc < 32; cc++) {
        float p = ps[r][cc];
        a0 += p * vs[cc][c];
        a1 += p * vs[cc][c + 32];
    }
    size_t ob = ((size_t)r * Tn + t) * Ff + h * 64;
    __nv_bfloat16 h0 = __float2bfloat16(a0);
    __nv_bfloat16 h1 = __float2bfloat16(a1);
    oh[ob + c]      = h0;  ol[ob + c]      = __float2bfloat16(a0 - __bfloat162float(h0));
    oh[ob + c + 32] = h1;  ol[ob + c + 32] = __float2bfloat16(a1 - __bfloat162float(h1));
}

// ---------------- bf16x3 HMMA GEMM, block 128x256, warp 64x64, k-chunk 32, 4 stages ----------------
#define STGB 49152
#define SMTOT (4*STGB)
// stage layout: Ah 0 (8KB), Al 8192, Wh 16384 (16KB), Wl 32768 (16KB)

template<int STATS>
__global__ void __launch_bounds__(256, 1)
k_gemm(const __nv_bfloat16* __restrict__ Ah, const __nv_bfloat16* __restrict__ Al,
       const __nv_bfloat16* __restrict__ Wh, const __nv_bfloat16* __restrict__ Wl,
       const float* __restrict__ bias, const float* __restrict__ res, float* __restrict__ out,
       float* __restrict__ bsum, float* __restrict__ bsqs)
{
    extern __shared__ __align__(1024) char smem[];
    const uint32_t sb = smem_u32(smem);
    const int tid = threadIdx.x, lane = tid & 31, wid = tid >> 5;
    const int n0 = blockIdx.x * 256;
    const size_t r0 = (size_t)blockIdx.y * 128;

    auto issue = [&](int i) {
        int k0 = i * 32;
        uint32_t st = sb + (i & 3) * STGB;
#pragma unroll
        for (int j = 0; j < 2; j++) {
            int u = tid + j * 256;
            int row = u >> 2, kg = u & 3;
            uint32_t off = SWZ64((uint32_t)(row * 64 + kg * 16));
            size_t ga = (r0 + row) * 512 + k0 + kg * 8;
            cp16(st + off,        Ah + ga);
            cp16(st + 8192 + off, Al + ga);
        }
#pragma unroll
        for (int j = 0; j < 4; j++) {
            int u = tid + j * 256;
            int row = u >> 2, kg = u & 3;
            uint32_t off = SWZ64((uint32_t)(row * 64 + kg * 16));
            size_t gb = (size_t)(n0 + row) * 512 + k0 + kg * 8;
            cp16(st + 16384 + off, Wh + gb);
            cp16(st + 32768 + off, Wl + gb);
        }
        CP_COMMIT();
    };

    float acc[4][8][4];
#pragma unroll
    for (int a = 0; a < 4; a++)
#pragma unroll
        for (int b = 0; b < 8; b++)
#pragma unroll
            for (int d = 0; d < 4; d++) acc[a][b][d] = 0.f;

    issue(0); issue(1); issue(2);

    const int wm = (wid & 1) * 64, wn = (wid >> 1) * 64;
    const int grp = lane >> 3, l7 = lane & 7;
    const int a_row = (grp & 1) * 8 + l7, a_kb = (grp >> 1) * 16;
    const int b_n   = (grp >> 1) * 8 + l7, b_kb = (grp & 1) * 16;

    for (int i = 0; i < 16; i++) {
        cp_wait<2>();
        __syncthreads();
        if (i + 3 < 16) issue(i + 3); else CP_COMMIT();
        const uint32_t stA  = sb + (i & 3) * STGB;
        const uint32_t stAl = stA + 8192, stBh = stA + 16384, stBl = stA + 32768;
#pragma unroll
        for (int ki = 0; ki < 2; ki++) {
            uint32_t ah[4][4], al[4][4];
#pragma unroll
            for (int mi = 0; mi < 4; mi++) {
                uint32_t off = SWZ64((uint32_t)((wm + mi * 16 + a_row) * 64 + ki * 32 + a_kb));
                ldmx4(ah[mi], stA + off);
                ldmx4(al[mi], stAl + off);
            }
#pragma unroll
            for (int pi = 0; pi < 4; pi++) {
                uint32_t off = SWZ64((uint32_t)((wn + pi * 16 + b_n) * 64 + ki * 32 + b_kb));
                uint32_t rh[4], rl[4];
                ldmx4(rh, stBh + off);
                ldmx4(rl, stBl + off);
#pragma unroll
                for (int mi = 0; mi < 4; mi++) {
                    mmabf(acc[mi][pi*2],   ah[mi], rh[0], rh[1]);
                    mmabf(acc[mi][pi*2],   ah[mi], rl[0], rl[1]);
                    mmabf(acc[mi][pi*2],   al[mi], rh[0], rh[1]);
                    mmabf(acc[mi][pi*2+1], ah[mi], rh[2], rh[3]);
                    mmabf(acc[mi][pi*2+1], ah[mi], rl[2], rl[3]);
                    mmabf(acc[mi][pi*2+1], al[mi], rh[2], rh[3]);
                }
            }
        }
        __syncthreads();
    }

    // epilogue: bias (+res) stores, optional fused per-batch stats
    const int erow = lane >> 2, ecol = (lane & 3) * 2;
    float s = 0.f, q = 0.f;
#pragma unroll
    for (int mi = 0; mi < 4; mi++) {
        size_t row0 = r0 + wm + mi * 16 + erow;
#pragma unroll
        for (int ni = 0; ni < 8; ni++) {
            int col = n0 + wn + ni * 8 + ecol;
            float2 bv = *(const float2*)(bias + col);
            float2 o0 = make_float2(acc[mi][ni][0] + bv.x, acc[mi][ni][1] + bv.y);
            float2 o1 = make_float2(acc[mi][ni][2] + bv.x, acc[mi][ni][3] + bv.y);
            size_t i0 = row0 * 512 + col, i1 = (row0 + 8) * 512 + col;
            if (res) {
                float2 r0v = *(const float2*)(res + i0), r1v = *(const float2*)(res + i1);
                o0.x += r0v.x; o0.y += r0v.y; o1.x += r1v.x; o1.y += r1v.y;
            }
            *(float2*)(out + i0) = o0;
            *(float2*)(out + i1) = o1;
            if (STATS) {
                s += o0.x + o0.y + o1.x + o1.y;
                q += o0.x*o0.x + o0.y*o0.y + o1.x*o1.x + o1.y*o1.y;
            }
        }
    }
    if (STATS) {
        for (int o = 16; o > 0; o >>= 1) { s += __shfl_down_sync(~0u, s, o); q += __shfl_down_sync(~0u, q, o); }
        static __shared__ float rs_[8], rq_[8];
        if (lane == 0) { rs_[wid] = s; rq_[wid] = q; }
        __syncthreads();
        if (tid == 0) {
            s = 0.f; q = 0.f;
            for (int j = 0; j < 8; j++) { s += rs_[j]; q += rq_[j]; }
            int bb = blockIdx.y >> 4;
            atomicAdd(&bsum[bb], s); atomicAdd(&bsqs[bb], q);
        }
    }
}

// ---------------- host ----------------
extern "C" void kernel_launch(void* const* d_in, const int* in_sizes, int n_in,
                              void* d_out, int out_size) {
    const float* x     = (const float*)d_in[0];
    const float* dw1_w = (const float*)d_in[1];
    const float* dw1_b = (const float*)d_in[2];
    const float* pw1_w = (const float*)d_in[3];
    const float* pw1_b = (const float*)d_in[4];
    const float* dw2_w = (const float*)d_in[5];
    const float* dw2_b = (const float*)d_in[6];
    const float* pw2_w = (const float*)d_in[7];
    const float* pw2_b = (const float*)d_in[8];
    const float* wq = (const float*)d_in[9];
    const float* bq = (const float*)d_in[10];
    const float* wk = (const float*)d_in[11];
    const float* bk = (const float*)d_in[12];
    const float* wv = (const float*)d_in[13];
    const float* bv = (const float*)d_in[14];
    const float* wp = (const float*)d_in[15];
    const float* bp = (const float*)d_in[16];
    const float* ff_w = (const float*)d_in[17];
    const float* ff_b = (const float*)d_in[18];
    float* out = (float*)d_out;

    float *A, *Q, *K, *V, *pe, *bsum, *bsqs, *tsum, *tsqs;
    __nv_bfloat16 *Dh, *Dl, *Wh, *Wl;
    cudaGetSymbolAddress((void**)&A,  g_A);
    cudaGetSymbolAddress((void**)&Q,  g_Q);
    cudaGetSymbolAddress((void**)&K,  g_K);
    cudaGetSymbolAddress((void**)&V,  g_V);
    cudaGetSymbolAddress((void**)&Dh, g_Dh);
    cudaGetSymbolAddress((void**)&Dl, g_Dl);
    cudaGetSymbolAddress((void**)&Wh, g_Wh);
    cudaGetSymbolAddress((void**)&Wl, g_Wl);
    cudaGetSymbolAddress((void**)&pe, g_pe);
    cudaGetSymbolAddress((void**)&bsum, g_bsum);
    cudaGetSymbolAddress((void**)&bsqs, g_bsqs);
    cudaGetSymbolAddress((void**)&tsum, g_tsum);
    cudaGetSymbolAddress((void**)&tsqs, g_tsqs);

    cudaFuncSetAttribute(k_gemm<0>, cudaFuncAttributeMaxDynamicSharedMemorySize, SMTOT);
    cudaFuncSetAttribute(k_gemm<1>, cudaFuncAttributeMaxDynamicSharedMemorySize, SMTOT);

    const size_t WSZ = 512 * 512;
    dim3 gemmGrid(2, 512);
    dim3 dwGrid(Tn / 16, Bsz);

    // weights -> bf16 hi/lo (order: pw1, pw2, wq, wk, wv, wp, ff)
    k_wconv7<<<dim3(256, 7), 256>>>(pw1_w, pw2_w, wq, wk, wv, wp, ff_w, Wh, Wl);

    // 1) x + pe (+ per-batch stats)
    k_pe<<<64, 256>>>(pe);
    k_zero2<<<1, 32>>>(bsum, bsqs, Bsz);
    k_addpe<<<NELT/4096, 1024>>>(x, pe, A, bsum, bsqs);

    // 2) LN + conv1 + pointwise1 (stats fused into GEMM epilogue)
    k_dw<<<dwGrid, 128>>>(A, bsum, bsqs, dw1_w, dw1_b, Dh, Dl);
    k_zero2<<<1, 32>>>(bsum, bsqs, Bsz);
    k_gemm<1><<<gemmGrid, 256, SMTOT>>>(Dh, Dl, Wh + 0*WSZ, Wl + 0*WSZ, pw1_b, nullptr, A, bsum, bsqs);

    // 3) 3x residual conv blocks (shared weights)
    for (int it = 0; it < 3; it++) {
        k_dw<<<dwGrid, 128>>>(A, bsum, bsqs, dw2_w, dw2_b, Dh, Dl);
        k_zero2<<<1, 32>>>(bsum, bsqs, Bsz);
        k_gemm<1><<<gemmGrid, 256, SMTOT>>>(Dh, Dl, Wh + 1*WSZ, Wl + 1*WSZ, pw2_b, A, A, bsum, bsqs);
    }

    // 4) per-batch LN -> split, QKV
    k_lnb<<<NELT/1024, 256>>>(A, bsum, bsqs, Dh, Dl);
    k_gemm<0><<<gemmGrid, 256, SMTOT>>>(Dh, Dl, Wh + 2*WSZ, Wl + 2*WSZ, bq, nullptr, Q, nullptr, nullptr);
    k_gemm<0><<<gemmGrid, 256, SMTOT>>>(Dh, Dl, Wh + 3*WSZ, Wl + 3*WSZ, bk, nullptr, K, nullptr, nullptr);
    k_gemm<0><<<gemmGrid, 256, SMTOT>>>(Dh, Dl, Wh + 4*WSZ, Wl + 4*WSZ, bv, nullptr, V, nullptr, nullptr);

    // 5) batch-axis attention
    k_attn<<<dim3(Tn, 8), dim3(32, 32)>>>(Q, K, V, Dh, Dl);

    // 6) output projection + residual
    k_gemm<0><<<gemmGrid, 256, SMTOT>>>(Dh, Dl, Wh + 5*WSZ, Wl + 5*WSZ, bp, A, A, nullptr, nullptr);

    // 7) final per-token LN + FF + residual -> d_out
    k_tstats<<<Tn, 256>>>(A, tsum, tsqs);
    k_lnt<<<NELT/1024, 256>>>(A, tsum, tsqs, Dh, Dl);
    k_gemm<0><<<gemmGrid, 256, SMTOT>>>(Dh, Dl, Wh + 6*WSZ, Wl + 6*WSZ, ff_b, A, out, nullptr, nullptr);
}